// round 5
// baseline (speedup 1.0000x reference)
#include <cuda_runtime.h>
#include <math.h>

// Problem constants
#define KDIM 128
#define BDIM 16
#define LDIM 8192
#define NF   256            // fine grid (oversampling sigma = 2)
#define WHALF 2.5f          // window half-width (w = 5)
#define BETA  11.5f         // ES beta = 2.30 * w
#define PI_F 3.14159265358979f

#define FSTRIDE 272         // fine-grid row stride (256 + 8 halo + 8 pad)
#define FBATCH  (NF * FSTRIDE)
#define LUTN 1600           // window LUT entries, step 1/512

typedef unsigned long long u64;

// Scratch (device globals; no cudaMalloc allowed)
__device__ float  d_phi[65];
__device__ float  d_ctab[256];
__device__ float  d_cos256[256];
__device__ float  d_corner[BDIM];
__device__ float2 d_wlut[LUTN];
__device__ float  d_g[BDIM * KDIM * NF];
__device__ float  d_f[BDIM * FBATCH];

__device__ __forceinline__ float es_win(float dist) {
    float z = dist * (1.0f / WHALF);
    float t = 1.0f - z * z;
    if (t <= 0.0f) return 0.0f;
    return expf(BETA * (sqrtf(t) - 1.0f));
}

// packed fp32x2 helpers (sm_100+)
__device__ __forceinline__ void fma2(u64& d, u64 a, u64 b) {
    asm("fma.rn.f32x2 %0, %1, %2, %0;" : "+l"(d) : "l"(a), "l"(b));
}
__device__ __forceinline__ u64 pack2(float v) {
    u64 r;
    asm("mov.b64 %0, {%1, %1};" : "=l"(r) : "f"(v));
    return r;
}

// ---------------------------------------------------------------------------
// Prep kernel, grid 89 x 256:
//  blocks 0..64  : Phi_k quadrature    blocks 65..71 : window LUT
//  blocks 72..87 : per-batch corner    block 88      : cos table
// ---------------------------------------------------------------------------
__global__ void prep_kernel(const float* __restrict__ psi) {
    int bid = blockIdx.x;
    int tid = threadIdx.x;

    if (bid < 65) {
        __shared__ float red[256];
        const int NQ = 512;
        float h = (2.0f * WHALF) / NQ;
        float k = (float)bid;
        float acc = 0.0f;
        #pragma unroll
        for (int r = 0; r < 2; r++) {
            int i = tid + r * 256;
            float t = -WHALF + (i + 0.5f) * h;
            acc += es_win(fabsf(t)) * cospif(k * t * (1.0f / 128.0f));
        }
        red[tid] = acc;
        __syncthreads();
        for (int s = 128; s > 0; s >>= 1) {
            if (tid < s) red[tid] += red[tid + s];
            __syncthreads();
        }
        if (tid == 0) d_phi[bid] = red[0] * h;
    } else if (bid < 72) {
        int i = (bid - 65) * 256 + tid;
        if (i < LUTN) {
            float h = 1.0f / 512.0f;
            float v0 = es_win((float)i * h);
            float v1 = es_win((float)(i + 1) * h);
            d_wlut[i] = make_float2(v0, v1 - v0);
        }
    } else if (bid < 88) {
        __shared__ float red[256];
        int b = bid - 72;
        const float* p = psi + b * (KDIM * KDIM);
        float acc = 0.0f;
        for (int idx = tid; idx < KDIM * KDIM; idx += 256) {
            float v = p[idx];
            int par = ((idx >> 7) ^ idx) & 1;
            acc += par ? -v : v;
        }
        red[tid] = acc;
        __syncthreads();
        for (int s = 128; s > 0; s >>= 1) {
            if (tid < s) red[tid] += red[tid + s];
            __syncthreads();
        }
        if (tid == 0) d_corner[b] = red[0];
    } else {
        d_cos256[tid] = cospif((float)tid * (1.0f / 128.0f));
    }
}

// ---------------------------------------------------------------------------
// c-table combine: trig via cos table.
// ---------------------------------------------------------------------------
__global__ void ctab_kernel() {
    __shared__ float sD[65];
    __shared__ float sc[256];
    int tid = threadIdx.x;
    sc[tid] = d_cos256[tid];
    if (tid < 65) sD[tid] = 1.0f / d_phi[tid];
    __syncthreads();
    int d = tid;
    float s = sD[0];
    #pragma unroll 8
    for (int k = 1; k < 64; k++) {
        s = fmaf(2.0f * sD[k], sc[(k * d) & 255], s);
    }
    s = fmaf(sD[64], sc[(64 * d) & 255], s);
    d_ctab[d] = s * (1.0f / 128.0f);
}

// ---------------------------------------------------------------------------
// Stage 1: g[b,m,v] = sum_n psi[b,m,n] * c[(v - 2n) mod 256]
// tile 16(m) x 128(v), 128 threads, micro 2x8 via f32x2.
// grid: (2 v, 8 m, 16 b)
// ---------------------------------------------------------------------------
__global__ void __launch_bounds__(128) stage1_kernel(const float* __restrict__ psi) {
    __shared__ float cs[256];
    __shared__ __align__(16) float As[16][18];
    __shared__ __align__(16) float Bs[16][132];
    int b  = blockIdx.z;
    int m0 = blockIdx.y * 16;
    int v0 = blockIdx.x * 128;
    int tid = threadIdx.x;
    cs[tid] = d_ctab[tid];
    cs[tid + 128] = d_ctab[tid + 128];
    int tx = tid & 15, ty = tid >> 4;     // tx: v/8 (0..15), ty: m/2 (0..7)
    u64 acc[2][4] = {};
    const float* P = psi + b * (KDIM * KDIM);

    for (int n0 = 0; n0 < KDIM; n0 += 16) {
        __syncthreads();
        {
            // As: 256 elems (r-major coalesced over psi)
            #pragma unroll
            for (int i = 0; i < 2; i++) {
                int e = tid + i * 128;
                int r = e >> 4, n = e & 15;
                As[n][r] = P[(m0 + r) * KDIM + n0 + n];
            }
            // Bs: 2048 elems
            #pragma unroll
            for (int i = 0; i < 16; i++) {
                int e = tid + i * 128;
                int n = e >> 7, v = e & 127;
                Bs[n][v] = cs[(v0 + v - 2 * (n0 + n)) & 255];
            }
        }
        __syncthreads();
        #pragma unroll
        for (int nk = 0; nk < 16; nk++) {
            float2 a = *(const float2*)&As[nk][ty * 2];
            u64 a0 = pack2(a.x), a1 = pack2(a.y);
            ulonglong2 b0 = *(const ulonglong2*)&Bs[nk][tx * 8];
            ulonglong2 b1 = *(const ulonglong2*)&Bs[nk][tx * 8 + 4];
            fma2(acc[0][0], a0, b0.x); fma2(acc[0][1], a0, b0.y);
            fma2(acc[0][2], a0, b1.x); fma2(acc[0][3], a0, b1.y);
            fma2(acc[1][0], a1, b0.x); fma2(acc[1][1], a1, b0.y);
            fma2(acc[1][2], a1, b1.x); fma2(acc[1][3], a1, b1.y);
        }
    }
    float* G = d_g + b * (KDIM * NF);
    #pragma unroll
    for (int i = 0; i < 2; i++) {
        float* row = &G[(m0 + ty * 2 + i) * NF + v0 + tx * 8];
        *(ulonglong2*)row       = make_ulonglong2(acc[i][0], acc[i][1]);
        *(ulonglong2*)(row + 4) = make_ulonglong2(acc[i][2], acc[i][3]);
    }
}

// ---------------------------------------------------------------------------
// Stage 2: f[b,u,v] = sum_m c[(u - 2m) mod 256] * g[b,m,v]
// tile 16(u) x 128(v), 128 threads, micro 2x8 via f32x2.
// grid: (2 v, 16 u, 16 b). Writes padded layout (+4 x offset) and x halo.
// ---------------------------------------------------------------------------
__global__ void __launch_bounds__(128) stage2_kernel() {
    __shared__ float cs[256];
    __shared__ __align__(16) float As[16][18];
    __shared__ __align__(16) float Bs[16][132];
    int b  = blockIdx.z;
    int u0 = blockIdx.y * 16;
    int v0 = blockIdx.x * 128;
    int tid = threadIdx.x;
    cs[tid] = d_ctab[tid];
    cs[tid + 128] = d_ctab[tid + 128];
    int tx = tid & 15, ty = tid >> 4;     // tx: v/8, ty: u/2
    u64 acc[2][4] = {};
    const float* G = d_g + b * (KDIM * NF);

    for (int m0 = 0; m0 < KDIM; m0 += 16) {
        __syncthreads();
        {
            #pragma unroll
            for (int i = 0; i < 2; i++) {
                int e = tid + i * 128;
                int k = e >> 4, r = e & 15;
                As[k][r] = cs[(u0 + r - 2 * (m0 + k)) & 255];
            }
            #pragma unroll
            for (int i = 0; i < 16; i++) {
                int e = tid + i * 128;
                int k = e >> 7, v = e & 127;
                Bs[k][v] = G[(m0 + k) * NF + v0 + v];
            }
        }
        __syncthreads();
        #pragma unroll
        for (int mk = 0; mk < 16; mk++) {
            float2 a = *(const float2*)&As[mk][ty * 2];
            u64 a0 = pack2(a.x), a1 = pack2(a.y);
            ulonglong2 b0 = *(const ulonglong2*)&Bs[mk][tx * 8];
            ulonglong2 b1 = *(const ulonglong2*)&Bs[mk][tx * 8 + 4];
            fma2(acc[0][0], a0, b0.x); fma2(acc[0][1], a0, b0.y);
            fma2(acc[0][2], a0, b1.x); fma2(acc[0][3], a0, b1.y);
            fma2(acc[1][0], a1, b0.x); fma2(acc[1][1], a1, b0.y);
            fma2(acc[1][2], a1, b1.x); fma2(acc[1][3], a1, b1.y);
        }
    }

    float* F = d_f + b * FBATCH;
    int col = v0 + tx * 8;
    #pragma unroll
    for (int i = 0; i < 2; i++) {
        int row = u0 + ty * 2 + i;
        float* rp = &F[row * FSTRIDE];
        *(ulonglong2*)(rp + col + 4) = make_ulonglong2(acc[i][0], acc[i][1]);
        *(ulonglong2*)(rp + col + 8) = make_ulonglong2(acc[i][2], acc[i][3]);
        if (col == 0)
            *(ulonglong2*)(rp + 260) = make_ulonglong2(acc[i][0], acc[i][1]); // right halo = cols 0..3
        if (col == 248)
            *(ulonglong2*)(rp + 0)   = make_ulonglong2(acc[i][2], acc[i][3]); // left halo = cols 252..255
    }
}

// ---------------------------------------------------------------------------
// Interpolation: one thread per point, w=5 ES window via shared LUT.
// ---------------------------------------------------------------------------
__global__ void interp_kernel(const float* __restrict__ x0,
                              const float* __restrict__ y0,
                              float* __restrict__ out) {
    __shared__ float2 slut[LUTN];
    int tid = threadIdx.x;
    for (int i = tid; i < LUTN; i += 256) slut[i] = d_wlut[i];
    __syncthreads();

    int p = blockIdx.x * 256 + tid;
    int b = p >> 13;
    float x = x0[p], y = y0[p];
    float txr = x * (128.0f / PI_F);
    float tyr = y * (128.0f / PI_F);
    float tx = txr + 256.0f;
    float ty = tyr + 256.0f;
    if (tx >= 256.0f) tx -= 256.0f;
    if (ty >= 256.0f) ty -= 256.0f;

    float fx = floorf(tx), fy = floorf(ty);
    int ix0 = (int)fx, iy0 = (int)fy;
    float dx = tx - fx, dy = ty - fy;

    int ic0 = ix0 - 2 + (dx >= 0.5f);
    int xb  = ic0 & ~3;
    int ir0 = iy0 - 2 + (dy >= 0.5f);

    float wx[8];
    #pragma unroll
    for (int j = 0; j < 8; j++) {
        float d  = fabsf(tx - (float)(xb + j));
        float fi = d * 512.0f;
        int idx  = (int)fi;
        float fr = fi - (float)idx;
        if (idx > LUTN - 1) { idx = LUTN - 1; fr = 0.0f; }
        float2 e = slut[idx];
        wx[j] = fmaf(fr, e.y, e.x);
    }
    float wy[5];
    #pragma unroll
    for (int a = 0; a < 5; a++) {
        float d  = fabsf(ty - (float)(ir0 + a));
        float fi = d * 512.0f;
        int idx  = (int)fi;
        float fr = fi - (float)idx;
        if (idx > LUTN - 1) { idx = LUTN - 1; fr = 0.0f; }
        float2 e = slut[idx];
        wy[a] = fmaf(fr, e.y, e.x);
    }

    const float* Fb = d_f + b * FBATCH;
    float acc = 0.0f;
    #pragma unroll
    for (int a = 0; a < 5; a++) {
        int row = (ir0 + a) & 255;
        const float4* rp = (const float4*)(Fb + row * FSTRIDE + xb + 4);
        float4 A = __ldg(rp);
        float4 Bv = __ldg(rp + 1);
        float rs = wx[0] * A.x + wx[1] * A.y + wx[2] * A.z + wx[3] * A.w
                 + wx[4] * Bv.x + wx[5] * Bv.y + wx[6] * Bv.z + wx[7] * Bv.w;
        acc = fmaf(wy[a], rs, acc);
    }

    float corr = d_corner[b] * (1.0f / 16384.0f) *
                 sinpif(0.5f * txr) * sinpif(0.5f * tyr);
    out[p] = acc - corr;
}

// ---------------------------------------------------------------------------
extern "C" void kernel_launch(void* const* d_in, const int* in_sizes, int n_in,
                              void* d_out, int out_size) {
    const float* x0  = (const float*)d_in[0];
    const float* y0  = (const float*)d_in[1];
    const float* psi = (const float*)d_in[2];
    float* out = (float*)d_out;

    prep_kernel<<<89, 256>>>(psi);
    ctab_kernel<<<1, 256>>>();
    stage1_kernel<<<dim3(2, 8, BDIM), 128>>>(psi);
    stage2_kernel<<<dim3(2, 16, BDIM), 128>>>();
    interp_kernel<<<512, 256>>>(x0, y0, out);
}

// round 6
// speedup vs baseline: 1.5680x; 1.5680x over previous
#include <cuda_runtime.h>
#include <math.h>

// Problem constants
#define KDIM 128
#define BDIM 16
#define LDIM 8192
#define NF   256            // fine grid (oversampling sigma = 2)
#define WHALF 2.5f          // window half-width (w = 5)
#define BETA  11.5f         // ES beta = 2.30 * w
#define PI_F 3.14159265358979f

#define FSTRIDE 272         // fine-grid row stride (256 + 8 halo + 8 pad)
#define FBATCH  (NF * FSTRIDE)
#define LUTN 1600           // window LUT entries, step 1/512

// Scratch (device globals; no cudaMalloc allowed)
__device__ float  d_phi[65];
__device__ float  d_ctab[256];
__device__ float  d_cos256[256];
__device__ float  d_corner[BDIM];
__device__ float2 d_wlut[LUTN];
__device__ float  d_g[BDIM * KDIM * NF];
__device__ float  d_f[BDIM * FBATCH];

__device__ __forceinline__ float es_win(float dist) {
    float z = dist * (1.0f / WHALF);
    float t = 1.0f - z * z;
    if (t <= 0.0f) return 0.0f;
    return expf(BETA * (sqrtf(t) - 1.0f));
}

// ---------------------------------------------------------------------------
// Prep kernel, grid 89 x 256:
//  blocks 0..64  : Phi_k quadrature    blocks 65..71 : window LUT
//  blocks 72..87 : per-batch corner    block 88      : cos table
// ---------------------------------------------------------------------------
__global__ void prep_kernel(const float* __restrict__ psi) {
    int bid = blockIdx.x;
    int tid = threadIdx.x;

    if (bid < 65) {
        __shared__ float red[256];
        const int NQ = 512;
        float h = (2.0f * WHALF) / NQ;
        float k = (float)bid;
        float acc = 0.0f;
        #pragma unroll
        for (int r = 0; r < 2; r++) {
            int i = tid + r * 256;
            float t = -WHALF + (i + 0.5f) * h;
            acc += es_win(fabsf(t)) * cospif(k * t * (1.0f / 128.0f));
        }
        red[tid] = acc;
        __syncthreads();
        for (int s = 128; s > 0; s >>= 1) {
            if (tid < s) red[tid] += red[tid + s];
            __syncthreads();
        }
        if (tid == 0) d_phi[bid] = red[0] * h;
    } else if (bid < 72) {
        int i = (bid - 65) * 256 + tid;
        if (i < LUTN) {
            float h = 1.0f / 512.0f;
            float v0 = es_win((float)i * h);
            float v1 = es_win((float)(i + 1) * h);
            d_wlut[i] = make_float2(v0, v1 - v0);
        }
    } else if (bid < 88) {
        __shared__ float red[256];
        int b = bid - 72;
        const float* p = psi + b * (KDIM * KDIM);
        float acc = 0.0f;
        for (int idx = tid; idx < KDIM * KDIM; idx += 256) {
            float v = p[idx];
            int par = ((idx >> 7) ^ idx) & 1;
            acc += par ? -v : v;
        }
        red[tid] = acc;
        __syncthreads();
        for (int s = 128; s > 0; s >>= 1) {
            if (tid < s) red[tid] += red[tid + s];
            __syncthreads();
        }
        if (tid == 0) d_corner[b] = red[0];
    } else {
        d_cos256[tid] = cospif((float)tid * (1.0f / 128.0f));
    }
}

// ---------------------------------------------------------------------------
// c-table combine: trig via cos table.
// ---------------------------------------------------------------------------
__global__ void ctab_kernel() {
    __shared__ float sD[65];
    __shared__ float sc[256];
    int tid = threadIdx.x;
    sc[tid] = d_cos256[tid];
    if (tid < 65) sD[tid] = 1.0f / d_phi[tid];
    __syncthreads();
    int d = tid;
    float s = sD[0];
    #pragma unroll 8
    for (int k = 1; k < 64; k++) {
        s = fmaf(2.0f * sD[k], sc[(k * d) & 255], s);
    }
    s = fmaf(sD[64], sc[(64 * d) & 255], s);
    d_ctab[d] = s * (1.0f / 128.0f);
}

// ---------------------------------------------------------------------------
// Stage 1: g[b,m,v] = sum_n psi[b,m,n] * c[(v - 2n) mod 256]
// tile 32(m) x 64(v), 128 threads, micro 4x4.
// A (psi) staged in smem per 32-wide k-chunk; B (ctab) read directly from
// a duplicated 512-entry table (no staging, no wrap AND in the hot loop).
// grid: (4 v, 4 m, 16 b)
// ---------------------------------------------------------------------------
__global__ void __launch_bounds__(128) stage1_kernel(const float* __restrict__ psi) {
    __shared__ float cs2[512];
    __shared__ __align__(16) float As[32][36];   // [m-local][n-local]
    int b  = blockIdx.z;
    int m0 = blockIdx.y * 32;
    int v0 = blockIdx.x * 64;
    int tid = threadIdx.x;
    #pragma unroll
    for (int i = 0; i < 4; i++)
        cs2[tid + i * 128] = d_ctab[(tid + i * 128) & 255];
    int tx = tid & 15, ty = tid >> 4;       // tx: v/4 (0..15), ty: m/4 (0..7)
    float acc[4][4] = {};
    const float* P = psi + b * (KDIM * KDIM);

    for (int n0 = 0; n0 < KDIM; n0 += 32) {
        __syncthreads();
        #pragma unroll
        for (int i = 0; i < 2; i++) {
            int u = tid + i * 128;           // float4 unit
            int ml = u >> 3, n4 = (u & 7) * 4;
            float4 a = *(const float4*)&P[(m0 + ml) * KDIM + n0 + n4];
            *(float4*)&As[ml][n4] = a;
        }
        __syncthreads();
        int bbase = v0 + tx * 4 + 256 - 2 * n0;
        #pragma unroll
        for (int nk = 0; nk < 32; nk++) {
            float av[4];
            #pragma unroll
            for (int i = 0; i < 4; i++) av[i] = As[ty * 4 + i][nk];   // broadcast
            int bi = bbase - 2 * nk;
            float2 b01 = *(const float2*)&cs2[bi];
            float2 b23 = *(const float2*)&cs2[bi + 2];
            float bv[4] = {b01.x, b01.y, b23.x, b23.y};
            #pragma unroll
            for (int i = 0; i < 4; i++)
                #pragma unroll
                for (int j = 0; j < 4; j++)
                    acc[i][j] = fmaf(av[i], bv[j], acc[i][j]);
        }
    }
    float* G = d_g + b * (KDIM * NF);
    #pragma unroll
    for (int i = 0; i < 4; i++) {
        float4 o = make_float4(acc[i][0], acc[i][1], acc[i][2], acc[i][3]);
        *(float4*)&G[(m0 + ty * 4 + i) * NF + v0 + tx * 4] = o;
    }
}

// ---------------------------------------------------------------------------
// Stage 2: f[b,u,v] = sum_m c[(u - 2m) mod 256] * g[b,m,v]
// tile 32(u) x 64(v), 128 threads, micro 4x4.
// B (g) staged in smem per 32-wide k-chunk; A (ctab) read directly from the
// duplicated table with broadcast LDS.64 (all tx lanes share the address).
// grid: (4 v, 8 u, 16 b). Writes padded layout (+4 x offset) and x halo.
// ---------------------------------------------------------------------------
__global__ void __launch_bounds__(128) stage2_kernel() {
    __shared__ float cs2[512];
    __shared__ __align__(16) float Bs[32][68];   // [m-local][v-local]
    int b  = blockIdx.z;
    int u0 = blockIdx.y * 32;
    int v0 = blockIdx.x * 64;
    int tid = threadIdx.x;
    #pragma unroll
    for (int i = 0; i < 4; i++)
        cs2[tid + i * 128] = d_ctab[(tid + i * 128) & 255];
    int tx = tid & 15, ty = tid >> 4;       // tx: v/4, ty: u/4
    float acc[4][4] = {};
    const float* G = d_g + b * (KDIM * NF);

    for (int m0 = 0; m0 < KDIM; m0 += 32) {
        __syncthreads();
        #pragma unroll
        for (int i = 0; i < 4; i++) {
            int u = tid + i * 128;           // float4 unit
            int mk = u >> 4, v4 = (u & 15) * 4;
            float4 g4 = *(const float4*)&G[(m0 + mk) * NF + v0 + v4];
            *(float4*)&Bs[mk][v4] = g4;
        }
        __syncthreads();
        int abase = u0 + ty * 4 + 256 - 2 * m0;
        #pragma unroll
        for (int mk = 0; mk < 32; mk++) {
            int ai = abase - 2 * mk;
            float2 a01 = *(const float2*)&cs2[ai];       // broadcast
            float2 a23 = *(const float2*)&cs2[ai + 2];   // broadcast
            float av[4] = {a01.x, a01.y, a23.x, a23.y};
            float4 bb = *(const float4*)&Bs[mk][tx * 4];
            float bv[4] = {bb.x, bb.y, bb.z, bb.w};
            #pragma unroll
            for (int i = 0; i < 4; i++)
                #pragma unroll
                for (int j = 0; j < 4; j++)
                    acc[i][j] = fmaf(av[i], bv[j], acc[i][j]);
        }
    }

    float* F = d_f + b * FBATCH;
    int col = v0 + tx * 4;
    #pragma unroll
    for (int i = 0; i < 4; i++) {
        int row = u0 + ty * 4 + i;
        float4 o = make_float4(acc[i][0], acc[i][1], acc[i][2], acc[i][3]);
        *(float4*)&F[row * FSTRIDE + col + 4] = o;
        if (col == 0)   *(float4*)&F[row * FSTRIDE + 260] = o;  // right halo
        if (col == 252) *(float4*)&F[row * FSTRIDE + 0]   = o;  // left halo
    }
}

// ---------------------------------------------------------------------------
// Interpolation: one thread per point, w=5 ES window via shared LUT.
// ---------------------------------------------------------------------------
__global__ void interp_kernel(const float* __restrict__ x0,
                              const float* __restrict__ y0,
                              float* __restrict__ out) {
    __shared__ float2 slut[LUTN];
    int tid = threadIdx.x;
    for (int i = tid; i < LUTN; i += 256) slut[i] = d_wlut[i];
    __syncthreads();

    int p = blockIdx.x * 256 + tid;
    int b = p >> 13;
    float x = x0[p], y = y0[p];
    float txr = x * (128.0f / PI_F);
    float tyr = y * (128.0f / PI_F);
    float tx = txr + 256.0f;
    float ty = tyr + 256.0f;
    if (tx >= 256.0f) tx -= 256.0f;
    if (ty >= 256.0f) ty -= 256.0f;

    float fx = floorf(tx), fy = floorf(ty);
    int ix0 = (int)fx, iy0 = (int)fy;
    float dx = tx - fx, dy = ty - fy;

    int ic0 = ix0 - 2 + (dx >= 0.5f);
    int xb  = ic0 & ~3;
    int ir0 = iy0 - 2 + (dy >= 0.5f);

    float wx[8];
    #pragma unroll
    for (int j = 0; j < 8; j++) {
        float d  = fabsf(tx - (float)(xb + j));
        float fi = d * 512.0f;
        int idx  = (int)fi;
        float fr = fi - (float)idx;
        if (idx > LUTN - 1) { idx = LUTN - 1; fr = 0.0f; }
        float2 e = slut[idx];
        wx[j] = fmaf(fr, e.y, e.x);
    }
    float wy[5];
    #pragma unroll
    for (int a = 0; a < 5; a++) {
        float d  = fabsf(ty - (float)(ir0 + a));
        float fi = d * 512.0f;
        int idx  = (int)fi;
        float fr = fi - (float)idx;
        if (idx > LUTN - 1) { idx = LUTN - 1; fr = 0.0f; }
        float2 e = slut[idx];
        wy[a] = fmaf(fr, e.y, e.x);
    }

    const float* Fb = d_f + b * FBATCH;
    float acc = 0.0f;
    #pragma unroll
    for (int a = 0; a < 5; a++) {
        int row = (ir0 + a) & 255;
        const float4* rp = (const float4*)(Fb + row * FSTRIDE + xb + 4);
        float4 A = __ldg(rp);
        float4 Bv = __ldg(rp + 1);
        float rs = wx[0] * A.x + wx[1] * A.y + wx[2] * A.z + wx[3] * A.w
                 + wx[4] * Bv.x + wx[5] * Bv.y + wx[6] * Bv.z + wx[7] * Bv.w;
        acc = fmaf(wy[a], rs, acc);
    }

    float corr = d_corner[b] * (1.0f / 16384.0f) *
                 sinpif(0.5f * txr) * sinpif(0.5f * tyr);
    out[p] = acc - corr;
}

// ---------------------------------------------------------------------------
extern "C" void kernel_launch(void* const* d_in, const int* in_sizes, int n_in,
                              void* d_out, int out_size) {
    const float* x0  = (const float*)d_in[0];
    const float* y0  = (const float*)d_in[1];
    const float* psi = (const float*)d_in[2];
    float* out = (float*)d_out;

    prep_kernel<<<89, 256>>>(psi);
    ctab_kernel<<<1, 256>>>();
    stage1_kernel<<<dim3(4, 4, BDIM), 128>>>(psi);
    stage2_kernel<<<dim3(4, 8, BDIM), 128>>>();
    interp_kernel<<<512, 256>>>(x0, y0, out);
}

// round 7
// speedup vs baseline: 1.5694x; 1.0009x over previous
#include <cuda_runtime.h>
#include <math.h>

// Problem constants
#define KDIM 128
#define BDIM 16
#define LDIM 8192
#define NF   256            // fine grid (oversampling sigma = 2)
#define WHALF 2.5f          // window half-width (w = 5)
#define BETA  11.5f         // ES beta = 2.30 * w
#define PI_F 3.14159265358979f

#define FSTRIDE 272         // fine-grid row stride (256 + 8 halo + 8 pad)
#define FBATCH  (NF * FSTRIDE)
#define LUTN 1600           // window LUT entries, step 1/512

// Scratch (device globals; no cudaMalloc allowed)
__device__ float  d_phi[65];
__device__ float  d_ctab[256];
__device__ float  d_cos256[256];
__device__ float  d_corner[BDIM];
__device__ float2 d_wlut[LUTN];
__device__ float  d_g[BDIM * KDIM * NF];
__device__ float  d_f[BDIM * FBATCH];

__device__ __forceinline__ float es_win(float dist) {
    float z = dist * (1.0f / WHALF);
    float t = 1.0f - z * z;
    if (t <= 0.0f) return 0.0f;
    return expf(BETA * (sqrtf(t) - 1.0f));
}

// ---------------------------------------------------------------------------
// Prep kernel, grid 89 x 256:
//  blocks 0..64  : Phi_k quadrature    blocks 65..71 : window LUT
//  blocks 72..87 : per-batch corner    block 88      : cos table
// ---------------------------------------------------------------------------
__global__ void prep_kernel(const float* __restrict__ psi) {
    int bid = blockIdx.x;
    int tid = threadIdx.x;

    if (bid < 65) {
        __shared__ float red[256];
        const int NQ = 512;
        float h = (2.0f * WHALF) / NQ;
        float k = (float)bid;
        float acc = 0.0f;
        #pragma unroll
        for (int r = 0; r < 2; r++) {
            int i = tid + r * 256;
            float t = -WHALF + (i + 0.5f) * h;
            acc += es_win(fabsf(t)) * cospif(k * t * (1.0f / 128.0f));
        }
        red[tid] = acc;
        __syncthreads();
        for (int s = 128; s > 0; s >>= 1) {
            if (tid < s) red[tid] += red[tid + s];
            __syncthreads();
        }
        if (tid == 0) d_phi[bid] = red[0] * h;
    } else if (bid < 72) {
        int i = (bid - 65) * 256 + tid;
        if (i < LUTN) {
            float h = 1.0f / 512.0f;
            float v0 = es_win((float)i * h);
            float v1 = es_win((float)(i + 1) * h);
            d_wlut[i] = make_float2(v0, v1 - v0);
        }
    } else if (bid < 88) {
        __shared__ float red[256];
        int b = bid - 72;
        const float* p = psi + b * (KDIM * KDIM);
        float acc = 0.0f;
        for (int idx = tid; idx < KDIM * KDIM; idx += 256) {
            float v = p[idx];
            int par = ((idx >> 7) ^ idx) & 1;
            acc += par ? -v : v;
        }
        red[tid] = acc;
        __syncthreads();
        for (int s = 128; s > 0; s >>= 1) {
            if (tid < s) red[tid] += red[tid + s];
            __syncthreads();
        }
        if (tid == 0) d_corner[b] = red[0];
    } else {
        d_cos256[tid] = cospif((float)tid * (1.0f / 128.0f));
    }
}

// ---------------------------------------------------------------------------
// c-table combine: trig via cos table.
// ---------------------------------------------------------------------------
__global__ void ctab_kernel() {
    __shared__ float sD[65];
    __shared__ float sc[256];
    int tid = threadIdx.x;
    sc[tid] = d_cos256[tid];
    if (tid < 65) sD[tid] = 1.0f / d_phi[tid];
    __syncthreads();
    int d = tid;
    float s = sD[0];
    #pragma unroll 8
    for (int k = 1; k < 64; k++) {
        s = fmaf(2.0f * sD[k], sc[(k * d) & 255], s);
    }
    s = fmaf(sD[64], sc[(64 * d) & 255], s);
    d_ctab[d] = s * (1.0f / 128.0f);
}

// ---------------------------------------------------------------------------
// Stage 1: g[b,m,v] = sum_n psi[b,m,n] * c[(v - 2n) mod 256]
// tile 32(m) x 64(v), 256 threads = 2 warpgroups, in-block K-split:
// wg0 sums n in [0,64), wg1 sums n in [64,128); combine via smem.
// Each wg uses the proven 4x4 micro-kernel (8x16 thread layout).
// grid: (4 v, 4 m, 16 b)
// ---------------------------------------------------------------------------
__global__ void __launch_bounds__(256) stage1_kernel(const float* __restrict__ psi) {
    __shared__ float cs2[512];
    __shared__ __align__(16) float As[2][32][36];   // per-wg [m-local][n-local]
    __shared__ __align__(16) float Red[32][68];
    int b  = blockIdx.z;
    int m0 = blockIdx.y * 32;
    int v0 = blockIdx.x * 64;
    int tid = threadIdx.x;
    cs2[tid]       = d_ctab[tid & 255];
    cs2[tid + 256] = d_ctab[tid & 255];
    int wg = tid >> 7, wtid = tid & 127;
    int tx = wtid & 15, ty = wtid >> 4;      // tx: v/4 (0..15), ty: m/4 (0..7)
    float acc[4][4] = {};
    const float* P = psi + b * (KDIM * KDIM);

    #pragma unroll
    for (int c = 0; c < 2; c++) {
        int n0 = wg * 64 + c * 32;
        __syncthreads();
        #pragma unroll
        for (int i = 0; i < 2; i++) {
            int u = wtid + i * 128;          // float4 units: 32 m x 8 n4
            int ml = u >> 3, n4 = (u & 7) * 4;
            *(float4*)&As[wg][ml][n4] = *(const float4*)&P[(m0 + ml) * KDIM + n0 + n4];
        }
        __syncthreads();
        int bbase = v0 + tx * 4 + 256 - 2 * n0;
        #pragma unroll
        for (int nk = 0; nk < 32; nk++) {
            float av[4];
            #pragma unroll
            for (int i = 0; i < 4; i++) av[i] = As[wg][ty * 4 + i][nk];
            int bi = bbase - 2 * nk;
            float2 b01 = *(const float2*)&cs2[bi];
            float2 b23 = *(const float2*)&cs2[bi + 2];
            float bv[4] = {b01.x, b01.y, b23.x, b23.y};
            #pragma unroll
            for (int i = 0; i < 4; i++)
                #pragma unroll
                for (int j = 0; j < 4; j++)
                    acc[i][j] = fmaf(av[i], bv[j], acc[i][j]);
        }
    }

    // combine the two K-halves
    if (wg == 0) {
        #pragma unroll
        for (int i = 0; i < 4; i++)
            *(float4*)&Red[ty * 4 + i][tx * 4] =
                make_float4(acc[i][0], acc[i][1], acc[i][2], acc[i][3]);
    }
    __syncthreads();
    if (wg == 1) {
        float* G = d_g + b * (KDIM * NF);
        #pragma unroll
        for (int i = 0; i < 4; i++) {
            float4 r = *(const float4*)&Red[ty * 4 + i][tx * 4];
            float4 o = make_float4(acc[i][0] + r.x, acc[i][1] + r.y,
                                   acc[i][2] + r.z, acc[i][3] + r.w);
            *(float4*)&G[(m0 + ty * 4 + i) * NF + v0 + tx * 4] = o;
        }
    }
}

// ---------------------------------------------------------------------------
// Stage 2: f[b,u,v] = sum_m c[(u - 2m) mod 256] * g[b,m,v]
// tile 32(u) x 64(v), 256 threads = 2 warpgroups, in-block K-split over m.
// grid: (4 v, 8 u, 16 b). Writes padded layout (+4 x offset) and x halo.
// ---------------------------------------------------------------------------
__global__ void __launch_bounds__(256) stage2_kernel() {
    __shared__ float cs2[512];
    __shared__ __align__(16) float Bs[2][32][68];   // per-wg [m-local][v-local]
    __shared__ __align__(16) float Red[32][68];
    int b  = blockIdx.z;
    int u0 = blockIdx.y * 32;
    int v0 = blockIdx.x * 64;
    int tid = threadIdx.x;
    cs2[tid]       = d_ctab[tid & 255];
    cs2[tid + 256] = d_ctab[tid & 255];
    int wg = tid >> 7, wtid = tid & 127;
    int tx = wtid & 15, ty = wtid >> 4;      // tx: v/4, ty: u/4
    float acc[4][4] = {};
    const float* G = d_g + b * (KDIM * NF);

    #pragma unroll
    for (int c = 0; c < 2; c++) {
        int m0 = wg * 64 + c * 32;
        __syncthreads();
        #pragma unroll
        for (int i = 0; i < 4; i++) {
            int u = wtid + i * 128;          // float4 units: 32 m x 16 v4
            int mk = u >> 4, v4 = (u & 15) * 4;
            *(float4*)&Bs[wg][mk][v4] = *(const float4*)&G[(m0 + mk) * NF + v0 + v4];
        }
        __syncthreads();
        int abase = u0 + ty * 4 + 256 - 2 * m0;
        #pragma unroll
        for (int mk = 0; mk < 32; mk++) {
            int ai = abase - 2 * mk;
            float2 a01 = *(const float2*)&cs2[ai];       // broadcast
            float2 a23 = *(const float2*)&cs2[ai + 2];   // broadcast
            float av[4] = {a01.x, a01.y, a23.x, a23.y};
            float4 bb = *(const float4*)&Bs[wg][mk][tx * 4];
            float bv[4] = {bb.x, bb.y, bb.z, bb.w};
            #pragma unroll
            for (int i = 0; i < 4; i++)
                #pragma unroll
                for (int j = 0; j < 4; j++)
                    acc[i][j] = fmaf(av[i], bv[j], acc[i][j]);
        }
    }

    // combine the two K-halves
    if (wg == 0) {
        #pragma unroll
        for (int i = 0; i < 4; i++)
            *(float4*)&Red[ty * 4 + i][tx * 4] =
                make_float4(acc[i][0], acc[i][1], acc[i][2], acc[i][3]);
    }
    __syncthreads();
    if (wg == 1) {
        float* F = d_f + b * FBATCH;
        int col = v0 + tx * 4;
        #pragma unroll
        for (int i = 0; i < 4; i++) {
            int row = u0 + ty * 4 + i;
            float4 r = *(const float4*)&Red[ty * 4 + i][tx * 4];
            float4 o = make_float4(acc[i][0] + r.x, acc[i][1] + r.y,
                                   acc[i][2] + r.z, acc[i][3] + r.w);
            *(float4*)&F[row * FSTRIDE + col + 4] = o;
            if (col == 0)   *(float4*)&F[row * FSTRIDE + 260] = o;  // right halo
            if (col == 252) *(float4*)&F[row * FSTRIDE + 0]   = o;  // left halo
        }
    }
}

// ---------------------------------------------------------------------------
// Interpolation: one thread per point, w=5 ES window via shared LUT.
// ---------------------------------------------------------------------------
__global__ void interp_kernel(const float* __restrict__ x0,
                              const float* __restrict__ y0,
                              float* __restrict__ out) {
    __shared__ float2 slut[LUTN];
    int tid = threadIdx.x;
    for (int i = tid; i < LUTN; i += 256) slut[i] = d_wlut[i];
    __syncthreads();

    int p = blockIdx.x * 256 + tid;
    int b = p >> 13;
    float x = x0[p], y = y0[p];
    float txr = x * (128.0f / PI_F);
    float tyr = y * (128.0f / PI_F);
    float tx = txr + 256.0f;
    float ty = tyr + 256.0f;
    if (tx >= 256.0f) tx -= 256.0f;
    if (ty >= 256.0f) ty -= 256.0f;

    float fx = floorf(tx), fy = floorf(ty);
    int ix0 = (int)fx, iy0 = (int)fy;
    float dx = tx - fx, dy = ty - fy;

    int ic0 = ix0 - 2 + (dx >= 0.5f);
    int xb  = ic0 & ~3;
    int ir0 = iy0 - 2 + (dy >= 0.5f);

    float wx[8];
    #pragma unroll
    for (int j = 0; j < 8; j++) {
        float d  = fabsf(tx - (float)(xb + j));
        float fi = d * 512.0f;
        int idx  = (int)fi;
        float fr = fi - (float)idx;
        if (idx > LUTN - 1) { idx = LUTN - 1; fr = 0.0f; }
        float2 e = slut[idx];
        wx[j] = fmaf(fr, e.y, e.x);
    }
    float wy[5];
    #pragma unroll
    for (int a = 0; a < 5; a++) {
        float d  = fabsf(ty - (float)(ir0 + a));
        float fi = d * 512.0f;
        int idx  = (int)fi;
        float fr = fi - (float)idx;
        if (idx > LUTN - 1) { idx = LUTN - 1; fr = 0.0f; }
        float2 e = slut[idx];
        wy[a] = fmaf(fr, e.y, e.x);
    }

    const float* Fb = d_f + b * FBATCH;
    float acc = 0.0f;
    #pragma unroll
    for (int a = 0; a < 5; a++) {
        int row = (ir0 + a) & 255;
        const float4* rp = (const float4*)(Fb + row * FSTRIDE + xb + 4);
        float4 A = __ldg(rp);
        float4 Bv = __ldg(rp + 1);
        float rs = wx[0] * A.x + wx[1] * A.y + wx[2] * A.z + wx[3] * A.w
                 + wx[4] * Bv.x + wx[5] * Bv.y + wx[6] * Bv.z + wx[7] * Bv.w;
        acc = fmaf(wy[a], rs, acc);
    }

    float corr = d_corner[b] * (1.0f / 16384.0f) *
                 sinpif(0.5f * txr) * sinpif(0.5f * tyr);
    out[p] = acc - corr;
}

// ---------------------------------------------------------------------------
extern "C" void kernel_launch(void* const* d_in, const int* in_sizes, int n_in,
                              void* d_out, int out_size) {
    const float* x0  = (const float*)d_in[0];
    const float* y0  = (const float*)d_in[1];
    const float* psi = (const float*)d_in[2];
    float* out = (float*)d_out;

    prep_kernel<<<89, 256>>>(psi);
    ctab_kernel<<<1, 256>>>();
    stage1_kernel<<<dim3(4, 4, BDIM), 256>>>(psi);
    stage2_kernel<<<dim3(4, 8, BDIM), 256>>>();
    interp_kernel<<<512, 256>>>(x0, y0, out);
}